// round 6
// baseline (speedup 1.0000x reference)
#include <cuda_runtime.h>
#include <cuda_fp16.h>
#include <stdint.h>

// ---------------- problem constants ----------------
#define D_IN    1024
#define D_OUT   1024
#define RANK    16
#define SCALING 2.0f          // alpha / rank = 32/16
#define M_MAX   32768         // B*S = 4*8192

// ---------------- GEMM tiling ----------------
#define TM      128
#define TN      128
#define KC      64            // k-chunk per stage
#define NCHUNK  (D_IN / KC)   // 16
#define STAGES  3
#define NTHR    256

#define TILE_B  (TM * KC * 2)         // 16384 bytes (128 rows x 64 fp16)
#define S_AHI   0
#define S_ALO   (1 * TILE_B)
#define S_BHI   (2 * TILE_B)
#define S_BLO   (3 * TILE_B)
#define STAGE_B (4 * TILE_B)          // 65536
#define SMEM_TOT (STAGES * STAGE_B)   // 196608

// ---------------- device scratch (static: no allocs allowed) ----------------
__device__ __align__(128) __half g_whi[D_OUT * D_IN];
__device__ __align__(128) __half g_wlo[D_OUT * D_IN];
__device__ __align__(128) __half g_xhi[(size_t)M_MAX * D_IN];
__device__ __align__(128) __half g_xlo[(size_t)M_MAX * D_IN];

// ---------------- helpers ----------------
__device__ __forceinline__ uint32_t smem_u32(const void* p) {
    uint32_t a;
    asm("{ .reg .u64 t; cvta.to.shared.u64 t, %1; cvt.u32.u64 %0, t; }"
        : "=r"(a) : "l"(p));
    return a;
}

__device__ __forceinline__ void cp16(uint32_t saddr, const void* gptr) {
    asm volatile("cp.async.cg.shared.global [%0], [%1], 16;"
                 :: "r"(saddr), "l"(gptr) : "memory");
}
#define CP_COMMIT()  asm volatile("cp.async.commit_group;" ::: "memory")
#define CP_WAIT(n)   asm volatile("cp.async.wait_group %0;" :: "n"(n) : "memory")

#define LDSM4(R, addr)                                                        \
    asm volatile("ldmatrix.sync.aligned.m8n8.x4.shared.b16 {%0,%1,%2,%3}, [%4];" \
                 : "=r"((R)[0]), "=r"((R)[1]), "=r"((R)[2]), "=r"((R)[3])     \
                 : "r"(addr))

// fp16 inputs, fp32 accumulate (half-rate) — high*high pass
#define MMA_F32(d, a, b0, b1)                                                 \
    asm volatile("mma.sync.aligned.m16n8k16.row.col.f32.f16.f16.f32 "         \
                 "{%0,%1,%2,%3}, {%4,%5,%6,%7}, {%8,%9}, {%0,%1,%2,%3};"      \
                 : "+f"((d)[0]), "+f"((d)[1]), "+f"((d)[2]), "+f"((d)[3])     \
                 : "r"((a)[0]), "r"((a)[1]), "r"((a)[2]), "r"((a)[3]),        \
                   "r"(b0), "r"(b1))

// fp16 inputs, fp16 accumulate (full-rate) — low-order correction passes
#define MMA_F16(d, a, b0, b1)                                                 \
    asm volatile("mma.sync.aligned.m16n8k16.row.col.f16.f16.f16.f16 "         \
                 "{%0,%1}, {%2,%3,%4,%5}, {%6,%7}, {%0,%1};"                  \
                 : "+r"((d)[0]), "+r"((d)[1])                                 \
                 : "r"((a)[0]), "r"((a)[1]), "r"((a)[2]), "r"((a)[3]),        \
                   "r"(b0), "r"(b1))

__device__ __forceinline__ uint32_t pack_hi(float a, float b, uint32_t& lo) {
    __half ha = __float2half_rn(a);
    __half hb = __float2half_rn(b);
    __half la = __float2half_rn(a - __half2float(ha));
    __half lb = __float2half_rn(b - __half2float(hb));
    lo = (uint32_t)__half_as_ushort(la) | ((uint32_t)__half_as_ushort(lb) << 16);
    return (uint32_t)__half_as_ushort(ha) | ((uint32_t)__half_as_ushort(hb) << 16);
}

// ---------------- prep 1: effective weight, scale-folded, fp16 hi/lo split ----------------
__global__ void __launch_bounds__(256) dora_prep_kernel(
    const float* __restrict__ W, const float* __restrict__ a_w,
    const float* __restrict__ b_w, const float* __restrict__ mag) {
    const int o = blockIdx.x;
    const int t = threadIdx.x;

    __shared__ float b_sh[RANK];
    __shared__ float red[256];
    __shared__ float scale_sh;

    if (t < RANK) b_sh[t] = b_w[o * RANK + t];
    __syncthreads();

    float vals[4];
    float ss = 0.0f;
#pragma unroll
    for (int i = 0; i < 4; i++) {
        int d = t + i * 256;
        float acc = W[(size_t)o * D_IN + d];
        float l = 0.0f;
#pragma unroll
        for (int r = 0; r < RANK; r++)
            l += b_sh[r] * a_w[r * D_IN + d];
        acc += SCALING * l;
        vals[i] = acc;
        ss += acc * acc;
    }

    red[t] = ss;
    __syncthreads();
#pragma unroll
    for (int s = 128; s > 0; s >>= 1) {
        if (t < s) red[t] += red[t + s];
        __syncthreads();
    }
    if (t == 0) scale_sh = mag[o] / sqrtf(red[0]);
    __syncthreads();
    const float scale = scale_sh;

#pragma unroll
    for (int i = 0; i < 4; i++) {
        int d = t + i * 256;
        float sv = vals[i] * scale;
        __half h = __float2half_rn(sv);
        __half l = __float2half_rn(sv - __half2float(h));
        g_whi[(size_t)o * D_IN + d] = h;
        g_wlo[(size_t)o * D_IN + d] = l;
    }
}

// ---------------- prep 2: x fp32 -> fp16 hi/lo global split ----------------
__global__ void __launch_bounds__(256) xsplit_kernel(const float* __restrict__ x, int total8) {
    int i = blockIdx.x * 256 + threadIdx.x;
    if (i >= total8) return;
    size_t base = (size_t)i * 8;
    float4 v0 = *reinterpret_cast<const float4*>(x + base);
    float4 v1 = *reinterpret_cast<const float4*>(x + base + 4);
    float f[8] = {v0.x, v0.y, v0.z, v0.w, v1.x, v1.y, v1.z, v1.w};
    uint32_t hw[4], lw[4];
#pragma unroll
    for (int j = 0; j < 4; j++)
        hw[j] = pack_hi(f[2 * j], f[2 * j + 1], lw[j]);
    *reinterpret_cast<uint4*>(g_xhi + base) = make_uint4(hw[0], hw[1], hw[2], hw[3]);
    *reinterpret_cast<uint4*>(g_xlo + base) = make_uint4(lw[0], lw[1], lw[2], lw[3]);
}

// ---------------- GEMM: out[M,1024] = x @ w_s^T ----------------
// pass structure per k16-step:
//   hi*hi -> fp32 acc (half-rate HMMA)
//   hi*lo + lo*hi -> shared fp16 acc (full-rate HMMA), added in epilogue
__global__ void __launch_bounds__(NTHR, 1) dora_gemm_kernel(float* __restrict__ out) {
    extern __shared__ char smem_raw[];
    const uint32_t sb = smem_u32(smem_raw);

    const int tid  = threadIdx.x;
    const int lane = tid & 31;
    const int warp = tid >> 5;
    const int n0 = blockIdx.x * TN;
    const int m0 = blockIdx.y * TM;

    // ---- per-thread cp.async offsets (4 iters x 4 buffers) ----
    // tile: 128 rows x 64 fp16 (128B rows). swizzle: byte ^ ((row&7)<<4).
    uint32_t soff[4];
    uint32_t goff[4];
#pragma unroll
    for (int i = 0; i < 4; i++) {
        int idx = tid + i * NTHR;          // 0..1023
        int row = idx >> 3;
        int c8  = idx & 7;                 // 16B chunk within row
        soff[i] = (uint32_t)(row * 128 + ((c8 * 16) ^ ((row & 7) << 4)));
        goff[i] = (uint32_t)(row * D_IN + c8 * 8);
    }
    const __half* xhiB = g_xhi + (size_t)m0 * D_IN;
    const __half* xloB = g_xlo + (size_t)m0 * D_IN;
    const __half* whiB = g_whi + (size_t)n0 * D_IN;
    const __half* wloB = g_wlo + (size_t)n0 * D_IN;

#define LOAD_STAGE(kc_, slot_)                                               \
    do {                                                                     \
        uint32_t k0_ = (uint32_t)(kc_) * KC;                                 \
        uint32_t b_ = sb + (uint32_t)(slot_) * STAGE_B;                      \
        _Pragma("unroll")                                                    \
        for (int i_ = 0; i_ < 4; i_++) {                                     \
            cp16(b_ + S_AHI + soff[i_], xhiB + goff[i_] + k0_);              \
            cp16(b_ + S_ALO + soff[i_], xloB + goff[i_] + k0_);              \
            cp16(b_ + S_BHI + soff[i_], whiB + goff[i_] + k0_);              \
            cp16(b_ + S_BLO + soff[i_], wloB + goff[i_] + k0_);              \
        }                                                                    \
    } while (0)

    // ---- warp tiling: 2 (M) x 4 (N); warp tile 64x32 ----
    const int wm = warp & 1;
    const int wn = warp >> 1;
    const int q = lane >> 3;
    const int r = lane & 7;

    uint32_t a_base[4], a_xor[4];
#pragma unroll
    for (int mt = 0; mt < 4; mt++) {
        int arow = wm * 64 + mt * 16 + (q & 1) * 8 + r;
        a_base[mt] = (uint32_t)(arow * 128);
        a_xor[mt]  = (uint32_t)((arow & 7) << 4);
    }
    const uint32_t a_kb = (uint32_t)((q >> 1) * 16);
    uint32_t b_base[2], b_xor[2];
#pragma unroll
    for (int bt = 0; bt < 2; bt++) {
        int brow = wn * 32 + bt * 16 + (q >> 1) * 8 + r;
        b_base[bt] = (uint32_t)(brow * 128);
        b_xor[bt]  = (uint32_t)((brow & 7) << 4);
    }
    const uint32_t b_kb = (uint32_t)((q & 1) * 16);

    float    accf[4][4][4];
    uint32_t acch[4][4][2];    // fp16x2 accumulators for the low-order passes
#pragma unroll
    for (int mt = 0; mt < 4; mt++)
#pragma unroll
        for (int nt = 0; nt < 4; nt++) {
#pragma unroll
            for (int j = 0; j < 4; j++) accf[mt][nt][j] = 0.0f;
            acch[mt][nt][0] = 0u;
            acch[mt][nt][1] = 0u;
        }

    // ---- pipeline prologue: prefetch 2 stages ----
    LOAD_STAGE(0, 0); CP_COMMIT();
    LOAD_STAGE(1, 1); CP_COMMIT();

    for (int kc = 0; kc < NCHUNK; kc++) {
        CP_WAIT(1);
        __syncthreads();

        if (kc + 2 < NCHUNK) LOAD_STAGE(kc + 2, (kc + 2) % STAGES);
        CP_COMMIT();

        const uint32_t sA = sb + (uint32_t)(kc % STAGES) * STAGE_B;
#pragma unroll
        for (int ks = 0; ks < 4; ks++) {
            const uint32_t akb = a_kb + (uint32_t)ks * 32;
            const uint32_t bkb = b_kb + (uint32_t)ks * 32;

            uint32_t AH[4][4], AL[4][4];
#pragma unroll
            for (int mt = 0; mt < 4; mt++) {
                uint32_t off = a_base[mt] + (akb ^ a_xor[mt]);
                LDSM4(AH[mt], sA + S_AHI + off);
                LDSM4(AL[mt], sA + S_ALO + off);
            }
            uint32_t BH[2][4], BL[2][4];
#pragma unroll
            for (int bt = 0; bt < 2; bt++) {
                uint32_t off = b_base[bt] + (bkb ^ b_xor[bt]);
                LDSM4(BH[bt], sA + S_BHI + off);
                LDSM4(BL[bt], sA + S_BLO + off);
            }
#pragma unroll
            for (int mt = 0; mt < 4; mt++) {
#pragma unroll
                for (int nt = 0; nt < 4; nt++) {
                    const int bt = nt >> 1, s = (nt & 1) * 2;
                    MMA_F32(accf[mt][nt], AH[mt], BH[bt][s], BH[bt][s + 1]);
                    MMA_F16(acch[mt][nt], AH[mt], BL[bt][s], BL[bt][s + 1]);
                    MMA_F16(acch[mt][nt], AL[mt], BH[bt][s], BH[bt][s + 1]);
                }
            }
        }
    }

    // ---- epilogue: combine fp32 + fp16 accumulators, direct global stores ----
    const int gm = lane >> 2;
    const int gn = (lane & 3) * 2;
#pragma unroll
    for (int mt = 0; mt < 4; mt++) {
#pragma unroll
        for (int nt = 0; nt < 4; nt++) {
            float2 lo01 = __half22float2(*reinterpret_cast<__half2*>(&acch[mt][nt][0]));
            float2 lo23 = __half22float2(*reinterpret_cast<__half2*>(&acch[mt][nt][1]));
            const int m = m0 + wm * 64 + mt * 16 + gm;
            const int n = n0 + wn * 32 + nt * 8 + gn;
            float2* p0 = reinterpret_cast<float2*>(out + (size_t)m * D_OUT + n);
            float2* p1 = reinterpret_cast<float2*>(out + (size_t)(m + 8) * D_OUT + n);
            *p0 = make_float2(accf[mt][nt][0] + lo01.x, accf[mt][nt][1] + lo01.y);
            *p1 = make_float2(accf[mt][nt][2] + lo23.x, accf[mt][nt][3] + lo23.y);
        }
    }
}

// ---------------- launch ----------------
extern "C" void kernel_launch(void* const* d_in, const int* in_sizes, int n_in,
                              void* d_out, int out_size) {
    const float* x   = (const float*)d_in[0];   // [B,S,D_IN]
    const float* W   = (const float*)d_in[1];   // [D_OUT, D_IN]
    const float* a_w = (const float*)d_in[2];   // [R, D_IN]
    const float* b_w = (const float*)d_in[3];   // [D_OUT, R]
    const float* mag = (const float*)d_in[4];   // [1, D_OUT]
    float* out = (float*)d_out;

    const int M = in_sizes[0] / D_IN;           // 32768

    dora_prep_kernel<<<D_OUT, 256>>>(W, a_w, b_w, mag);

    const int total8 = M * D_IN / 8;
    xsplit_kernel<<<(total8 + 255) / 256, 256>>>(x, total8);

    cudaFuncSetAttribute(dora_gemm_kernel,
                         cudaFuncAttributeMaxDynamicSharedMemorySize, SMEM_TOT);
    dim3 grid(D_OUT / TN, M / TM);              // (8, 256) — n fastest: x L2 reuse
    dora_gemm_kernel<<<grid, NTHR, SMEM_TOT>>>(out);
}

// round 7
// speedup vs baseline: 2.4625x; 2.4625x over previous
#include <cuda_runtime.h>
#include <cuda_fp16.h>
#include <stdint.h>

// ---------------- problem constants ----------------
#define D_IN    1024
#define D_OUT   1024
#define RANK    16
#define SCALING 2.0f          // alpha / rank = 32/16
#define M_MAX   32768         // B*S = 4*8192

// ---------------- GEMM tiling ----------------
#define TM      128
#define TN      128
#define KC      64            // k-chunk per stage
#define NCHUNK  (D_IN / KC)   // 16
#define STAGES  3
#define NTHR    256

#define TILE_B  (TM * KC * 2)         // 16384 bytes (128 rows x 64 fp16)
#define S_A     0
#define S_B     TILE_B
#define STAGE_B (2 * TILE_B)          // 32768
#define SMEM_TOT (STAGES * STAGE_B)   // 98304 -> 2 CTAs/SM

// ---------------- device scratch (static: no allocs allowed) ----------------
__device__ __align__(128) __half g_wh[D_OUT * D_IN];
__device__ __align__(128) __half g_xh[(size_t)M_MAX * D_IN];

// ---------------- helpers ----------------
__device__ __forceinline__ uint32_t smem_u32(const void* p) {
    uint32_t a;
    asm("{ .reg .u64 t; cvta.to.shared.u64 t, %1; cvt.u32.u64 %0, t; }"
        : "=r"(a) : "l"(p));
    return a;
}

__device__ __forceinline__ void cp16(uint32_t saddr, const void* gptr) {
    asm volatile("cp.async.cg.shared.global [%0], [%1], 16;"
                 :: "r"(saddr), "l"(gptr) : "memory");
}
#define CP_COMMIT()  asm volatile("cp.async.commit_group;" ::: "memory")
#define CP_WAIT(n)   asm volatile("cp.async.wait_group %0;" :: "n"(n) : "memory")

#define LDSM4(R, addr)                                                        \
    asm volatile("ldmatrix.sync.aligned.m8n8.x4.shared.b16 {%0,%1,%2,%3}, [%4];" \
                 : "=r"((R)[0]), "=r"((R)[1]), "=r"((R)[2]), "=r"((R)[3])     \
                 : "r"(addr))

// fp16 inputs, fp32 accumulate
#define MMA_F32(d, a, b0, b1)                                                 \
    asm volatile("mma.sync.aligned.m16n8k16.row.col.f32.f16.f16.f32 "         \
                 "{%0,%1,%2,%3}, {%4,%5,%6,%7}, {%8,%9}, {%0,%1,%2,%3};"      \
                 : "+f"((d)[0]), "+f"((d)[1]), "+f"((d)[2]), "+f"((d)[3])     \
                 : "r"((a)[0]), "r"((a)[1]), "r"((a)[2]), "r"((a)[3]),        \
                   "r"(b0), "r"(b1))

// ---------------- prep 1: effective weight, scale-folded -> fp16 ----------------
__global__ void __launch_bounds__(256) dora_prep_kernel(
    const float* __restrict__ W, const float* __restrict__ a_w,
    const float* __restrict__ b_w, const float* __restrict__ mag) {
    const int o = blockIdx.x;
    const int t = threadIdx.x;

    __shared__ float b_sh[RANK];
    __shared__ float red[256];
    __shared__ float scale_sh;

    if (t < RANK) b_sh[t] = b_w[o * RANK + t];
    __syncthreads();

    float vals[4];
    float ss = 0.0f;
#pragma unroll
    for (int i = 0; i < 4; i++) {
        int d = t + i * 256;
        float acc = W[(size_t)o * D_IN + d];
        float l = 0.0f;
#pragma unroll
        for (int r = 0; r < RANK; r++)
            l += b_sh[r] * a_w[r * D_IN + d];
        acc += SCALING * l;
        vals[i] = acc;
        ss += acc * acc;
    }

    red[t] = ss;
    __syncthreads();
#pragma unroll
    for (int s = 128; s > 0; s >>= 1) {
        if (t < s) red[t] += red[t + s];
        __syncthreads();
    }
    if (t == 0) scale_sh = mag[o] / sqrtf(red[0]);
    __syncthreads();
    const float scale = scale_sh;

#pragma unroll
    for (int i = 0; i < 4; i++) {
        int d = t + i * 256;
        g_wh[(size_t)o * D_IN + d] = __float2half_rn(vals[i] * scale);
    }
}

// ---------------- prep 2: x fp32 -> fp16 ----------------
__global__ void __launch_bounds__(256) xsplit_kernel(const float* __restrict__ x, int total8) {
    int i = blockIdx.x * 256 + threadIdx.x;
    if (i >= total8) return;
    size_t base = (size_t)i * 8;
    float4 v0 = *reinterpret_cast<const float4*>(x + base);
    float4 v1 = *reinterpret_cast<const float4*>(x + base + 4);
    __half2 h0 = __floats2half2_rn(v0.x, v0.y);
    __half2 h1 = __floats2half2_rn(v0.z, v0.w);
    __half2 h2 = __floats2half2_rn(v1.x, v1.y);
    __half2 h3 = __floats2half2_rn(v1.z, v1.w);
    *reinterpret_cast<uint4*>(g_xh + base) = make_uint4(
        *reinterpret_cast<uint32_t*>(&h0), *reinterpret_cast<uint32_t*>(&h1),
        *reinterpret_cast<uint32_t*>(&h2), *reinterpret_cast<uint32_t*>(&h3));
}

// ---------------- GEMM: out[M,1024] = x_h @ w_h^T (fp32 accum) ----------------
__global__ void __launch_bounds__(NTHR, 2) dora_gemm_kernel(float* __restrict__ out) {
    extern __shared__ char smem_raw[];
    const uint32_t sb = smem_u32(smem_raw);

    const int tid  = threadIdx.x;
    const int lane = tid & 31;
    const int warp = tid >> 5;
    const int n0 = blockIdx.x * TN;
    const int m0 = blockIdx.y * TM;

    // ---- per-thread cp.async offsets ----
    // tile: 128 rows x 64 fp16 (128B rows). swizzle: byte ^ ((row&7)<<4).
    // 1024 16B-chunks per tile; 256 threads -> 4 iters, A and B each.
    uint32_t soff[4];
    uint32_t goff[4];
#pragma unroll
    for (int i = 0; i < 4; i++) {
        int idx = tid + i * NTHR;          // 0..1023
        int row = idx >> 3;
        int c8  = idx & 7;                 // 16B chunk within row
        soff[i] = (uint32_t)(row * 128 + ((c8 * 16) ^ ((row & 7) << 4)));
        goff[i] = (uint32_t)(row * D_IN + c8 * 8);
    }
    const __half* xB = g_xh + (size_t)m0 * D_IN;
    const __half* wB = g_wh + (size_t)n0 * D_IN;

#define LOAD_STAGE(kc_, slot_)                                               \
    do {                                                                     \
        uint32_t k0_ = (uint32_t)(kc_) * KC;                                 \
        uint32_t b_ = sb + (uint32_t)(slot_) * STAGE_B;                      \
        _Pragma("unroll")                                                    \
        for (int i_ = 0; i_ < 4; i_++) {                                     \
            cp16(b_ + S_A + soff[i_], xB + goff[i_] + k0_);                  \
            cp16(b_ + S_B + soff[i_], wB + goff[i_] + k0_);                  \
        }                                                                    \
    } while (0)

    // ---- warp tiling: 2 (M) x 4 (N); warp tile 64x32 ----
    const int wm = warp & 1;
    const int wn = warp >> 1;
    const int q = lane >> 3;
    const int r = lane & 7;

    uint32_t a_base[4], a_xor[4];
#pragma unroll
    for (int mt = 0; mt < 4; mt++) {
        int arow = wm * 64 + mt * 16 + (q & 1) * 8 + r;
        a_base[mt] = (uint32_t)(arow * 128);
        a_xor[mt]  = (uint32_t)((arow & 7) << 4);
    }
    const uint32_t a_kb = (uint32_t)((q >> 1) * 16);
    uint32_t b_base[2], b_xor[2];
#pragma unroll
    for (int bt = 0; bt < 2; bt++) {
        int brow = wn * 32 + bt * 16 + (q >> 1) * 8 + r;
        b_base[bt] = (uint32_t)(brow * 128);
        b_xor[bt]  = (uint32_t)((brow & 7) << 4);
    }
    const uint32_t b_kb = (uint32_t)((q & 1) * 16);

    float acc[4][4][4];
#pragma unroll
    for (int mt = 0; mt < 4; mt++)
#pragma unroll
        for (int nt = 0; nt < 4; nt++)
#pragma unroll
            for (int j = 0; j < 4; j++) acc[mt][nt][j] = 0.0f;

    // ---- pipeline prologue: prefetch 2 stages ----
    LOAD_STAGE(0, 0); CP_COMMIT();
    LOAD_STAGE(1, 1); CP_COMMIT();

    for (int kc = 0; kc < NCHUNK; kc++) {
        CP_WAIT(1);
        __syncthreads();

        if (kc + 2 < NCHUNK) LOAD_STAGE(kc + 2, (kc + 2) % STAGES);
        CP_COMMIT();

        const uint32_t sA = sb + (uint32_t)(kc % STAGES) * STAGE_B;
#pragma unroll
        for (int ks = 0; ks < 4; ks++) {
            const uint32_t akb = a_kb + (uint32_t)ks * 32;
            const uint32_t bkb = b_kb + (uint32_t)ks * 32;

            uint32_t A[4][4];
#pragma unroll
            for (int mt = 0; mt < 4; mt++) {
                uint32_t off = a_base[mt] + (akb ^ a_xor[mt]);
                LDSM4(A[mt], sA + S_A + off);
            }
            uint32_t B[2][4];
#pragma unroll
            for (int bt = 0; bt < 2; bt++) {
                uint32_t off = b_base[bt] + (bkb ^ b_xor[bt]);
                LDSM4(B[bt], sA + S_B + off);
            }
#pragma unroll
            for (int mt = 0; mt < 4; mt++) {
#pragma unroll
                for (int nt = 0; nt < 4; nt++) {
                    const int bt = nt >> 1, s = (nt & 1) * 2;
                    MMA_F32(acc[mt][nt], A[mt], B[bt][s], B[bt][s + 1]);
                }
            }
        }
    }

    // ---- epilogue: direct global stores ----
    const int gm = lane >> 2;
    const int gn = (lane & 3) * 2;
#pragma unroll
    for (int mt = 0; mt < 4; mt++) {
#pragma unroll
        for (int nt = 0; nt < 4; nt++) {
            const int m = m0 + wm * 64 + mt * 16 + gm;
            const int n = n0 + wn * 32 + nt * 8 + gn;
            float2* p0 = reinterpret_cast<float2*>(out + (size_t)m * D_OUT + n);
            float2* p1 = reinterpret_cast<float2*>(out + (size_t)(m + 8) * D_OUT + n);
            *p0 = make_float2(acc[mt][nt][0], acc[mt][nt][1]);
            *p1 = make_float2(acc[mt][nt][2], acc[mt][nt][3]);
        }
    }
}

// ---------------- launch ----------------
extern "C" void kernel_launch(void* const* d_in, const int* in_sizes, int n_in,
                              void* d_out, int out_size) {
    const float* x   = (const float*)d_in[0];   // [B,S,D_IN]
    const float* W   = (const float*)d_in[1];   // [D_OUT, D_IN]
    const float* a_w = (const float*)d_in[2];   // [R, D_IN]
    const float* b_w = (const float*)d_in[3];   // [D_OUT, R]
    const float* mag = (const float*)d_in[4];   // [1, D_OUT]
    float* out = (float*)d_out;

    const int M = in_sizes[0] / D_IN;           // 32768

    dora_prep_kernel<<<D_OUT, 256>>>(W, a_w, b_w, mag);

    const int total8 = M * D_IN / 8;
    xsplit_kernel<<<(total8 + 255) / 256, 256>>>(x, total8);

    cudaFuncSetAttribute(dora_gemm_kernel,
                         cudaFuncAttributeMaxDynamicSharedMemorySize, SMEM_TOT);
    dim3 grid(D_OUT / TN, M / TM);              // (8, 256) — n fastest: x L2 reuse
    dora_gemm_kernel<<<grid, NTHR, SMEM_TOT>>>(out);
}